// round 12
// baseline (speedup 1.0000x reference)
#include <cuda_runtime.h>
#include <cuda_bf16.h>
#include <cstdint>
#include <math.h>

// ================= Problem constants =================
#define Bc 8
#define Ntok 4096
#define Cch 512
#define NHI 1024

typedef __nv_bfloat16 bf16;

// ================= Scratch =================
__device__ float g_out_hi[Bc * NHI * Cch];

__device__ bf16 g_xhih[Bc * NHI * Cch], g_xhil[Bc * NHI * Cch];
__device__ bf16 g_Wqh[1536 * 512], g_Wql[1536 * 512];
__device__ bf16 g_qh[(size_t)Bc * NHI * 1536], g_ql[(size_t)Bc * NHI * 1536];
__device__ bf16 g_winh[(size_t)Bc * Ntok * Cch], g_winl[(size_t)Bc * Ntok * Cch];
__device__ bf16 g_Wloh[1536 * 512], g_Wlol[1536 * 512];
__device__ bf16 g_qloh[(size_t)Bc * 1024 * 4 * 1536], g_qlol[(size_t)Bc * 1024 * 4 * 1536];
__device__ bf16 g_sumh[(size_t)Bc * Ntok * Cch], g_suml[(size_t)Bc * Ntok * Cch];
__device__ bf16 g_Wph[512 * 512], g_Wpl[512 * 512];

// ================= helpers =================
__device__ __forceinline__ uint32_t smem_to_u32(const void* p) {
    uint32_t a;
    asm("{ .reg .u64 t; cvta.to.shared.u64 t, %1; cvt.u32.u64 %0, t; }" : "=r"(a) : "l"(p));
    return a;
}

__device__ __forceinline__ void cp16(uint32_t s, const void* g) {
    asm volatile("cp.async.cg.shared.global [%0], [%1], 16;" :: "r"(s), "l"(g) : "memory");
}
__device__ __forceinline__ void cp_commit() {
    asm volatile("cp.async.commit_group;" ::: "memory");
}
template <int N>
__device__ __forceinline__ void cp_wait() {
    asm volatile("cp.async.wait_group %0;" :: "n"(N) : "memory");
}

__device__ __forceinline__ void ldm4(uint32_t* r, uint32_t addr) {
    asm volatile("ldmatrix.sync.aligned.m8n8.x4.shared.b16 {%0,%1,%2,%3}, [%4];"
        : "=r"(r[0]), "=r"(r[1]), "=r"(r[2]), "=r"(r[3]) : "r"(addr));
}
__device__ __forceinline__ void ldm4t(uint32_t* r, uint32_t addr) {
    asm volatile("ldmatrix.sync.aligned.m8n8.x4.trans.shared.b16 {%0,%1,%2,%3}, [%4];"
        : "=r"(r[0]), "=r"(r[1]), "=r"(r[2]), "=r"(r[3]) : "r"(addr));
}

__device__ __forceinline__ void mma16816(float* c, const uint32_t* a, uint32_t b0, uint32_t b1) {
    asm volatile(
        "mma.sync.aligned.m16n8k16.row.col.f32.bf16.bf16.f32 "
        "{%0,%1,%2,%3}, {%4,%5,%6,%7}, {%8,%9}, {%0,%1,%2,%3};"
        : "+f"(c[0]), "+f"(c[1]), "+f"(c[2]), "+f"(c[3])
        : "r"(a[0]), "r"(a[1]), "r"(a[2]), "r"(a[3]), "r"(b0), "r"(b1));
}

__device__ __forceinline__ void psplit2(float x, float y, uint32_t& hp, uint32_t& lp) {
    bf16 hx = __float2bfloat16(x), hy = __float2bfloat16(y);
    bf16 lx = __float2bfloat16(x - __bfloat162float(hx));
    bf16 ly = __float2bfloat16(y - __bfloat162float(hy));
    hp = (uint32_t)*(uint16_t*)&hx | ((uint32_t)*(uint16_t*)&hy << 16);
    lp = (uint32_t)*(uint16_t*)&lx | ((uint32_t)*(uint16_t*)&ly << 16);
}

// ================= split-bf16 GEMM via mma.sync =================
// OUTMODE: 0 = fp32 C, 1 = fp32 C + bias, 2 = split bf16 (Ch, Cl)
template <int NT, int OUTMODE>
__global__ void __launch_bounds__(NT == 128 ? 256 : 128) mma_gemm(
    const bf16* __restrict__ Ah, const bf16* __restrict__ Al, int lda, long long sAb, long long sAh,
    const bf16* __restrict__ Bh, const bf16* __restrict__ Bl, int ldb, long long sBb, long long sBh,
    float* __restrict__ C, bf16* __restrict__ Ch, bf16* __restrict__ Cl,
    int ldc, long long sCb, long long sCh,
    const float* __restrict__ bias, int K, float alpha, int hdiv)
{
    constexpr int THREADS = (NT == 128) ? 256 : 128;
    constexpr int NWC = NT / 32;
    constexpr int BBYTES = NT * 128;
    constexpr int STAGE = 32768 + 2 * BBYTES;

    extern __shared__ __align__(1024) char smem[];
    uint32_t sb = smem_to_u32(smem);
    int tid = threadIdx.x, wid = tid >> 5, lane = tid & 31;
    int wr = wid / NWC, wc = wid % NWC;

    int z = blockIdx.z, zb = z / hdiv, zh = z - zb * hdiv;
    long long offA = zb * sAb + zh * sAh;
    long long offB = zb * sBb + zh * sBh;
    Ah += offA; Al += offA; Bh += offB; Bl += offB;
    long long offC = zb * sCb + zh * sCh;
    int bm = blockIdx.y * 128, bn = blockIdx.x * NT;

    float acc[4][4][4];
#pragma unroll
    for (int i = 0; i < 4; i++)
#pragma unroll
        for (int j = 0; j < 4; j++)
#pragma unroll
            for (int t = 0; t < 4; t++) acc[i][j][t] = 0.f;

    int NC = K >> 6;

    auto issue = [&](int c) {
        int s = c & 1;
        int k0 = c * 64;
        uint32_t sbase = sb + s * STAGE;
#pragma unroll
        for (int i = 0; i < 1024 / THREADS; i++) {
            int idx = tid + i * THREADS;
            int row = idx >> 3, c16 = idx & 7;
            uint32_t d = (uint32_t)(row * 128 + ((c16 ^ (row & 7)) << 4));
            size_t go = (size_t)(bm + row) * lda + k0 + c16 * 8;
            cp16(sbase + d, Ah + go);
            cp16(sbase + 16384 + d, Al + go);
        }
#pragma unroll
        for (int i = 0; i < (NT * 8) / THREADS; i++) {
            int idx = tid + i * THREADS;
            int row = idx >> 3, c16 = idx & 7;
            uint32_t d = (uint32_t)(row * 128 + ((c16 ^ (row & 7)) << 4));
            size_t go = (size_t)(bn + row) * ldb + k0 + c16 * 8;
            cp16(sbase + 32768 + d, Bh + go);
            cp16(sbase + 32768 + BBYTES + d, Bl + go);
        }
        cp_commit();
    };

    issue(0);

    for (int c = 0; c < NC; c++) {
        if (c + 1 < NC) { issue(c + 1); cp_wait<1>(); }
        else            { cp_wait<0>(); }
        __syncthreads();

        uint32_t Ab = sb + (c & 1) * STAGE;
        uint32_t Bb = Ab + 32768;
#pragma unroll
        for (int ks = 0; ks < 4; ks++) {
            uint32_t ah[4][4], al[4][4];
#pragma unroll
            for (int i = 0; i < 4; i++) {
                int row = wr * 64 + i * 16 + (lane & 15);
                int c16 = ks * 2 + (lane >> 4);
                uint32_t ad = (uint32_t)(row * 128 + ((c16 ^ (row & 7)) << 4));
                ldm4(ah[i], Ab + ad);
                ldm4(al[i], Ab + 16384 + ad);
            }
            uint32_t bh[8], bl[8];
#pragma unroll
            for (int j2 = 0; j2 < 2; j2++) {
                int nrow = wc * 32 + j2 * 16 + ((lane >> 4) << 3) + (lane & 7);
                int c16 = ks * 2 + ((lane >> 3) & 1);
                uint32_t bd = (uint32_t)(nrow * 128 + ((c16 ^ (nrow & 7)) << 4));
                ldm4(&bh[j2 * 4], Bb + bd);
                ldm4(&bl[j2 * 4], Bb + BBYTES + bd);
            }
#pragma unroll
            for (int i = 0; i < 4; i++)
#pragma unroll
                for (int j = 0; j < 4; j++) {
                    mma16816(acc[i][j], ah[i], bh[j * 2], bh[j * 2 + 1]);
                    mma16816(acc[i][j], ah[i], bl[j * 2], bl[j * 2 + 1]);
                    mma16816(acc[i][j], al[i], bh[j * 2], bh[j * 2 + 1]);
                }
        }
        __syncthreads();
    }

    int r = lane >> 2, cp2 = (lane & 3) * 2;
#pragma unroll
    for (int i = 0; i < 4; i++) {
        int row = bm + wr * 64 + i * 16 + r;
#pragma unroll
        for (int j = 0; j < 4; j++) {
            int col = bn + wc * 32 + j * 8 + cp2;
            float2 v0, v1;
            v0.x = acc[i][j][0] * alpha; v0.y = acc[i][j][1] * alpha;
            v1.x = acc[i][j][2] * alpha; v1.y = acc[i][j][3] * alpha;
            if (OUTMODE == 1) {
                float b0 = bias[col], b1 = bias[col + 1];
                v0.x += b0; v0.y += b1; v1.x += b0; v1.y += b1;
            }
            if (OUTMODE == 2) {
                uint32_t hp, lp;
                psplit2(v0.x, v0.y, hp, lp);
                *(uint32_t*)&Ch[(offC + (size_t)row * ldc + col)] = hp;
                *(uint32_t*)&Cl[(offC + (size_t)row * ldc + col)] = lp;
                psplit2(v1.x, v1.y, hp, lp);
                *(uint32_t*)&Ch[(offC + (size_t)(row + 8) * ldc + col)] = hp;
                *(uint32_t*)&Cl[(offC + (size_t)(row + 8) * ldc + col)] = lp;
            } else {
                *(float2*)&C[offC + (size_t)row * ldc + col] = v0;
                *(float2*)&C[offC + (size_t)(row + 8) * ldc + col] = v1;
            }
        }
    }
}

// ================= FlashAttention-2 style hi-branch attention =================
__global__ void __launch_bounds__(128) flash_hi(
    const bf16* __restrict__ Qh, const bf16* __restrict__ Ql, float* __restrict__ outhi)
{
    extern __shared__ __align__(1024) char smem[];
    uint32_t sb = smem_to_u32(smem);
    const uint32_t sQh = sb, sQl = sb + 16384;
    int tid = threadIdx.x, wid = tid >> 5, lane = tid & 31;
    int mtile = blockIdx.x, bh = blockIdx.y;
    int b = bh >> 3, h = bh & 7;

    size_t qbase = ((size_t)(b * 1024) + mtile * 128) * 1536 + h * 64;
#pragma unroll
    for (int i = 0; i < 8; i++) {
        int idx = tid + i * 128;
        int row = idx >> 3, c16 = idx & 7;
        uint32_t d = (uint32_t)(row * 128 + ((c16 ^ (row & 7)) << 4));
        size_t go = qbase + (size_t)row * 1536 + c16 * 8;
        cp16(sQh + d, Qh + go);
        cp16(sQl + d, Ql + go);
    }
    cp_commit();

    auto issueKV = [&](int t) {
        uint32_t kb = sb + 32768 + (t & 1) * 32768;
        size_t kbase = ((size_t)(b * 1024) + t * 64) * 1536 + 512 + h * 64;
#pragma unroll
        for (int i = 0; i < 4; i++) {
            int idx = tid + i * 128;
            int row = idx >> 3, c16 = idx & 7;
            uint32_t d = (uint32_t)(row * 128 + ((c16 ^ (row & 7)) << 4));
            size_t go = kbase + (size_t)row * 1536 + c16 * 8;
            cp16(kb + d, Qh + go);
            cp16(kb + 8192 + d, Ql + go);
            cp16(kb + 16384 + d, Qh + go + 512);
            cp16(kb + 24576 + d, Ql + go + 512);
        }
        cp_commit();
    };
    issueKV(0);
    issueKV(1);

    int rbase = wid * 32;
    float o[2][8][4];
    float mrow[2][2], lrow[2][2];
#pragma unroll
    for (int mi = 0; mi < 2; mi++) {
#pragma unroll
        for (int j = 0; j < 8; j++)
#pragma unroll
            for (int e = 0; e < 4; e++) o[mi][j][e] = 0.f;
        mrow[mi][0] = -INFINITY; mrow[mi][1] = -INFINITY;
        lrow[mi][0] = 0.f; lrow[mi][1] = 0.f;
    }

    for (int t = 0; t < 16; t++) {
        if (t < 15) cp_wait<1>(); else cp_wait<0>();
        __syncthreads();
        uint32_t kb = sb + 32768 + (t & 1) * 32768;

        float s[2][8][4];
#pragma unroll
        for (int mi = 0; mi < 2; mi++)
#pragma unroll
            for (int j = 0; j < 8; j++)
#pragma unroll
                for (int e = 0; e < 4; e++) s[mi][j][e] = 0.f;

#pragma unroll
        for (int kd = 0; kd < 4; kd++) {
            uint32_t aqh[2][4], aql[2][4];
#pragma unroll
            for (int mi = 0; mi < 2; mi++) {
                int row = rbase + mi * 16 + (lane & 15);
                int c16 = kd * 2 + (lane >> 4);
                uint32_t ad = (uint32_t)(row * 128 + ((c16 ^ (row & 7)) << 4));
                ldm4(aqh[mi], sQh + ad);
                ldm4(aql[mi], sQl + ad);
            }
            uint32_t bkh[16], bkl[16];
#pragma unroll
            for (int j2 = 0; j2 < 4; j2++) {
                int nrow = j2 * 16 + ((lane >> 4) << 3) + (lane & 7);
                int c16 = kd * 2 + ((lane >> 3) & 1);
                uint32_t bd = (uint32_t)(nrow * 128 + ((c16 ^ (nrow & 7)) << 4));
                ldm4(&bkh[j2 * 4], kb + bd);
                ldm4(&bkl[j2 * 4], kb + 8192 + bd);
            }
#pragma unroll
            for (int mi = 0; mi < 2; mi++)
#pragma unroll
                for (int j = 0; j < 8; j++) {
                    mma16816(s[mi][j], aqh[mi], bkh[j * 2], bkh[j * 2 + 1]);
                    mma16816(s[mi][j], aqh[mi], bkl[j * 2], bkl[j * 2 + 1]);
                    mma16816(s[mi][j], aql[mi], bkh[j * 2], bkh[j * 2 + 1]);
                }
        }

#pragma unroll
        for (int mi = 0; mi < 2; mi++)
#pragma unroll
            for (int j = 0; j < 8; j++)
#pragma unroll
                for (int e = 0; e < 4; e++) s[mi][j][e] *= 0.125f;

#pragma unroll
        for (int mi = 0; mi < 2; mi++)
#pragma unroll
            for (int hf = 0; hf < 2; hf++) {
                float tm = -INFINITY;
#pragma unroll
                for (int j = 0; j < 8; j++)
                    tm = fmaxf(tm, fmaxf(s[mi][j][hf * 2], s[mi][j][hf * 2 + 1]));
                tm = fmaxf(tm, __shfl_xor_sync(0xffffffffu, tm, 1));
                tm = fmaxf(tm, __shfl_xor_sync(0xffffffffu, tm, 2));
                float mnew = fmaxf(mrow[mi][hf], tm);
                float corr = __expf(mrow[mi][hf] - mnew);
                mrow[mi][hf] = mnew;
                float rs = 0.f;
#pragma unroll
                for (int j = 0; j < 8; j++) {
                    float p0 = __expf(s[mi][j][hf * 2] - mnew);
                    float p1 = __expf(s[mi][j][hf * 2 + 1] - mnew);
                    s[mi][j][hf * 2] = p0; s[mi][j][hf * 2 + 1] = p1;
                    rs += p0 + p1;
                }
                rs += __shfl_xor_sync(0xffffffffu, rs, 1);
                rs += __shfl_xor_sync(0xffffffffu, rs, 2);
                lrow[mi][hf] = lrow[mi][hf] * corr + rs;
#pragma unroll
                for (int j = 0; j < 8; j++) {
                    o[mi][j][hf * 2] *= corr; o[mi][j][hf * 2 + 1] *= corr;
                }
            }

#pragma unroll
        for (int tt = 0; tt < 4; tt++) {
            uint32_t aph[2][4], apl[2][4];
#pragma unroll
            for (int mi = 0; mi < 2; mi++) {
                psplit2(s[mi][2 * tt][0], s[mi][2 * tt][1], aph[mi][0], apl[mi][0]);
                psplit2(s[mi][2 * tt][2], s[mi][2 * tt][3], aph[mi][1], apl[mi][1]);
                psplit2(s[mi][2 * tt + 1][0], s[mi][2 * tt + 1][1], aph[mi][2], apl[mi][2]);
                psplit2(s[mi][2 * tt + 1][2], s[mi][2 * tt + 1][3], aph[mi][3], apl[mi][3]);
            }
            uint32_t bvh[16], bvl[16];
#pragma unroll
            for (int j2 = 0; j2 < 4; j2++) {
                int vrow = tt * 16 + ((lane >> 3) & 1) * 8 + (lane & 7);
                int c16 = j2 * 2 + (lane >> 4);
                uint32_t vd = (uint32_t)(vrow * 128 + ((c16 ^ (vrow & 7)) << 4));
                ldm4t(&bvh[j2 * 4], kb + 16384 + vd);
                ldm4t(&bvl[j2 * 4], kb + 24576 + vd);
            }
#pragma unroll
            for (int mi = 0; mi < 2; mi++)
#pragma unroll
                for (int j = 0; j < 8; j++) {
                    mma16816(o[mi][j], aph[mi], bvh[j * 2], bvh[j * 2 + 1]);
                    mma16816(o[mi][j], aph[mi], bvl[j * 2], bvl[j * 2 + 1]);
                    mma16816(o[mi][j], apl[mi], bvh[j * 2], bvh[j * 2 + 1]);
                }
        }
        __syncthreads();
        if (t + 2 < 16) issueKV(t + 2);
    }

    size_t obase = ((size_t)(b * 1024) + mtile * 128) * 512 + h * 64;
    int r = lane >> 2, c2 = (lane & 3) * 2;
#pragma unroll
    for (int mi = 0; mi < 2; mi++)
#pragma unroll
        for (int hf = 0; hf < 2; hf++) {
            float inv = 1.f / lrow[mi][hf];
            int grow = rbase + mi * 16 + hf * 8 + r;
#pragma unroll
            for (int j = 0; j < 8; j++) {
                float2 v;
                v.x = o[mi][j][hf * 2] * inv;
                v.y = o[mi][j][hf * 2 + 1] * inv;
                *(float2*)&outhi[obase + (size_t)grow * 512 + j * 8 + c2] = v;
            }
        }
}

// ================= prep kernels =================
__device__ __forceinline__ void split4(float4 v, bf16* h, bf16* l, size_t base)
{
    float a[4] = { v.x, v.y, v.z, v.w };
    bf16 hh[4], ll[4];
#pragma unroll
    for (int i = 0; i < 4; i++) {
        hh[i] = __float2bfloat16(a[i]);
        ll[i] = __float2bfloat16(a[i] - __bfloat162float(hh[i]));
    }
    *(uint2*)(h + base) = *(uint2*)hh;
    *(uint2*)(l + base) = *(uint2*)ll;
}

__global__ void split_generic(const float4* __restrict__ src, bf16* __restrict__ h,
                              bf16* __restrict__ l, int n4)
{
    int gid = blockIdx.x * 256 + threadIdx.x;
    if (gid >= n4) return;
    split4(src[gid], h, l, (size_t)gid * 4);
}

__global__ void pool_split(const float* __restrict__ x)
{
    int gid = blockIdx.x * 256 + threadIdx.x;
    int c4 = gid & 127;
    int hw = (gid >> 7) & 1023;
    int b = gid >> 17;
    int wh = hw >> 5, ww = hw & 31;
    int n0 = (wh * 2) * 64 + ww * 2;
    const float4* xb = (const float4*)(x + (size_t)b * Ntok * Cch);
    float4 a = xb[(size_t)n0 * 128 + c4];
    float4 bv = xb[(size_t)(n0 + 1) * 128 + c4];
    float4 c = xb[(size_t)(n0 + 64) * 128 + c4];
    float4 d = xb[(size_t)(n0 + 65) * 128 + c4];
    float4 o;
    o.x = (a.x + bv.x + c.x + d.x) * 0.25f;
    o.y = (a.y + bv.y + c.y + d.y) * 0.25f;
    o.z = (a.z + bv.z + c.z + d.z) * 0.25f;
    o.w = (a.w + bv.w + c.w + d.w) * 0.25f;
    split4(o, g_xhih, g_xhil, (size_t)gid * 4);
}

__global__ void gather_win_split(const float* __restrict__ x)
{
    int gid = blockIdx.x * 256 + threadIdx.x;
    int k4 = gid & 127;
    int m = gid >> 7;
    int t = m & 3, w = (m >> 2) & 1023, b = m >> 12;
    int kp = k4 * 4;
    int p = kp >> 7, q = kp & 127;
    int wh = w >> 5, ww = w & 31;
    int i = p >> 1, j = p & 1;
    int n = (wh * 2 + i) * 64 + ww * 2 + j;
    float4 v = *(const float4*)(x + ((size_t)b * Ntok + n) * Cch + t * 128 + q);
    split4(v, g_winh, g_winl, (size_t)gid * 4);
}

__global__ void permw_split(const float* __restrict__ W)
{
    int gid = blockIdx.x * 256 + threadIdx.x;
    if (gid >= 1536 * 512) return;
    int kp = gid & 511, j = gid >> 9;
    int p = kp >> 7, q = kp & 127;
    float v = W[j * 512 + q * 4 + p];
    bf16 h = __float2bfloat16(v);
    g_Wloh[gid] = h;
    g_Wlol[gid] = __float2bfloat16(v - __bfloat162float(h));
}

// ===== lo-branch 4x4 windowed attention + fused bilinear upsample of out_hi =====
// reads split-bf16 qkv_lo (g_qloh/g_qlol) and g_out_hi; writes split-bf16 sum.
__global__ void lo_attn_fused()
{
    __shared__ __align__(16) float sm[2][4 * 1536];
    int wp = threadIdx.x >> 5;
    int lane = threadIdx.x & 31;
    int widx = blockIdx.x * 2 + wp;
    int b = widx >> 10, w = widx & 1023;

    // reconstruct fp32 qkv for this window from split bf16
    {
        const uint4* ph = (const uint4*)(g_qloh + (size_t)widx * 4 * 1536);
        const uint4* pl = (const uint4*)(g_qlol + (size_t)widx * 4 * 1536);
        float* dst = sm[wp];
        for (int f = lane; f < 768; f += 32) {
            uint4 uh = ph[f], ul = pl[f];
            const bf16* hh = (const bf16*)&uh;
            const bf16* ll = (const bf16*)&ul;
            float v[8];
#pragma unroll
            for (int e = 0; e < 8; e++)
                v[e] = __bfloat162float(hh[e]) + __bfloat162float(ll[e]);
            *(float4*)&dst[f * 8] = *(float4*)&v[0];
            *(float4*)&dst[f * 8 + 4] = *(float4*)&v[4];
        }
    }
    __syncwarp();

    int h = lane >> 2, ti = lane & 3;
    const float* base = sm[wp];
    const float4* q4 = (const float4*)(base + ti * 1536 + h * 64);
    float s[4];
#pragma unroll
    for (int tj = 0; tj < 4; tj++) {
        const float4* k4 = (const float4*)(base + tj * 1536 + 512 + h * 64);
        float acc = 0.f;
#pragma unroll
        for (int d = 0; d < 16; d++) {
            float4 a = q4[d], kk = k4[d];
            acc += a.x * kk.x + a.y * kk.y + a.z * kk.z + a.w * kk.w;
        }
        s[tj] = acc * 0.125f;
    }
    float mx = fmaxf(fmaxf(s[0], s[1]), fmaxf(s[2], s[3]));
    float p[4], sum = 0.f;
#pragma unroll
    for (int tj = 0; tj < 4; tj++) { p[tj] = __expf(s[tj] - mx); sum += p[tj]; }
    float inv = 1.f / sum;
#pragma unroll
    for (int tj = 0; tj < 4; tj++) p[tj] *= inv;

    int wh = w >> 5, ww = w & 31;
    int i = ti >> 1, j = ti & 1;
    // bilinear neighbor rows/weights on the 32x32 pooled grid (half-pixel, clamped)
    int ya, yb2; float wya, wyb;
    if (i == 0) { ya = wh - 1 < 0 ? 0 : wh - 1; yb2 = wh; wya = 0.25f; wyb = 0.75f; }
    else        { ya = wh; yb2 = wh + 1 > 31 ? 31 : wh + 1; wya = 0.75f; wyb = 0.25f; }
    int xa, xb2; float wxa, wxb;
    if (j == 0) { xa = ww - 1 < 0 ? 0 : ww - 1; xb2 = ww; wxa = 0.25f; wxb = 0.75f; }
    else        { xa = ww; xb2 = ww + 1 > 31 ? 31 : ww + 1; wxa = 0.75f; wxb = 0.25f; }
    float waa = wya * wxa, wab = wya * wxb, wba = wyb * wxa, wbb = wyb * wxb;

    const float* ohb = g_out_hi + (size_t)b * NHI * Cch + h * 64;
    const float4* r00 = (const float4*)(ohb + (size_t)(ya * 32 + xa) * 512);
    const float4* r01 = (const float4*)(ohb + (size_t)(ya * 32 + xb2) * 512);
    const float4* r10 = (const float4*)(ohb + (size_t)(yb2 * 32 + xa) * 512);
    const float4* r11 = (const float4*)(ohb + (size_t)(yb2 * 32 + xb2) * 512);

    int nout = (wh * 2 + i) * 64 + ww * 2 + j;
    size_t obase = ((size_t)b * Ntok + nout) * Cch + h * 64;
    const float4* v0 = (const float4*)(base + 0 * 1536 + 1024 + h * 64);
    const float4* v1 = (const float4*)(base + 1 * 1536 + 1024 + h * 64);
    const float4* v2 = (const float4*)(base + 2 * 1536 + 1024 + h * 64);
    const float4* v3 = (const float4*)(base + 3 * 1536 + 1024 + h * 64);
#pragma unroll
    for (int d = 0; d < 16; d++) {
        float4 uaa = r00[d], uab = r01[d], uba = r10[d], ubb = r11[d];
        float4 o;
        o.x = waa * uaa.x + wab * uab.x + wba * uba.x + wbb * ubb.x;
        o.y = waa * uaa.y + wab * uab.y + wba * uba.y + wbb * ubb.y;
        o.z = waa * uaa.z + wab * uab.z + wba * uba.z + wbb * ubb.z;
        o.w = waa * uaa.w + wab * uab.w + wba * uba.w + wbb * ubb.w;
        float4 a = v0[d], bb = v1[d], c = v2[d], e = v3[d];
        o.x += p[0] * a.x + p[1] * bb.x + p[2] * c.x + p[3] * e.x;
        o.y += p[0] * a.y + p[1] * bb.y + p[2] * c.y + p[3] * e.y;
        o.z += p[0] * a.z + p[1] * bb.z + p[2] * c.z + p[3] * e.z;
        o.w += p[0] * a.w + p[1] * bb.w + p[2] * c.w + p[3] * e.w;
        split4(o, g_sumh, g_suml, obase + d * 4);
    }
}

// ================= Launch =================
extern "C" void kernel_launch(void* const* d_in, const int* in_sizes, int n_in,
                              void* d_out, int out_size)
{
    const float* x = (const float*)d_in[0];
    const float* Wqkv = (const float*)d_in[1];
    const float* Wproj = (const float*)d_in[2];
    const float* bproj = (const float*)d_in[3];
    float* out = (float*)d_out;

    float* outhi;
    bf16 *xhih, *xhil, *Wqh, *Wql, *qh, *ql;
    bf16 *winh, *winl, *Wloh, *Wlol, *qloh, *qlol, *sumh, *suml, *Wph, *Wpl;
    cudaGetSymbolAddress((void**)&outhi, g_out_hi);
    cudaGetSymbolAddress((void**)&xhih, g_xhih);
    cudaGetSymbolAddress((void**)&xhil, g_xhil);
    cudaGetSymbolAddress((void**)&Wqh, g_Wqh);
    cudaGetSymbolAddress((void**)&Wql, g_Wql);
    cudaGetSymbolAddress((void**)&qh, g_qh);
    cudaGetSymbolAddress((void**)&ql, g_ql);
    cudaGetSymbolAddress((void**)&winh, g_winh);
    cudaGetSymbolAddress((void**)&winl, g_winl);
    cudaGetSymbolAddress((void**)&Wloh, g_Wloh);
    cudaGetSymbolAddress((void**)&Wlol, g_Wlol);
    cudaGetSymbolAddress((void**)&qloh, g_qloh);
    cudaGetSymbolAddress((void**)&qlol, g_qlol);
    cudaGetSymbolAddress((void**)&sumh, g_sumh);
    cudaGetSymbolAddress((void**)&suml, g_suml);
    cudaGetSymbolAddress((void**)&Wph, g_Wph);
    cudaGetSymbolAddress((void**)&Wpl, g_Wpl);

    const int SMEM128 = 2 * (32768 + 2 * 128 * 128);  // 131072
    const int SMEMFA  = 32768 + 2 * 32768;            //  98304
    cudaFuncSetAttribute(mma_gemm<128, 0>, cudaFuncAttributeMaxDynamicSharedMemorySize, SMEM128);
    cudaFuncSetAttribute(mma_gemm<128, 1>, cudaFuncAttributeMaxDynamicSharedMemorySize, SMEM128);
    cudaFuncSetAttribute(mma_gemm<128, 2>, cudaFuncAttributeMaxDynamicSharedMemorySize, SMEM128);
    cudaFuncSetAttribute(flash_hi, cudaFuncAttributeMaxDynamicSharedMemorySize, SMEMFA);

    // input prep
    pool_split<<<4096, 256>>>(x);
    split_generic<<<768, 256>>>((const float4*)Wqkv, Wqh, Wql, 196608);
    gather_win_split<<<16384, 256>>>(x);
    permw_split<<<3072, 256>>>(Wqkv);
    split_generic<<<256, 256>>>((const float4*)Wproj, Wph, Wpl, 65536);

    // qkv_hi = x_hi @ W_qkv^T : [8192 x 1536], K=512 -> split bf16 qh/ql
    mma_gemm<128, 2><<<dim3(12, 64, 1), 256, SMEM128>>>(
        xhih, xhil, 512, 0, 0, Wqh, Wql, 512, 0, 0,
        nullptr, qh, ql, 1536, 0, 0, nullptr, 512, 1.f, 1);

    // fused hi attention -> out_hi fp32
    flash_hi<<<dim3(8, 64), 128, SMEMFA>>>(qh, ql, outhi);

    // qkv_lo = windows @ W_lo^T : [32768 x 1536], K=512 -> split bf16
    mma_gemm<128, 2><<<dim3(12, 256, 1), 256, SMEM128>>>(
        winh, winl, 512, 0, 0, Wloh, Wlol, 512, 0, 0,
        nullptr, qloh, qlol, 1536, 0, 0, nullptr, 512, 1.f, 1);

    // lo attention + fused bilinear upsample of out_hi -> split bf16 sum
    lo_attn_fused<<<4096, 64>>>();

    // out = sum @ W_proj^T + b : [32768 x 512], K=512
    mma_gemm<128, 1><<<dim3(4, 256, 1), 256, SMEM128>>>(
        sumh, suml, 512, 0, 0, Wph, Wpl, 512, 0, 0,
        out, nullptr, nullptr, 512, 0, 0, bproj, 512, 1.f, 1);
}